// round 4
// baseline (speedup 1.0000x reference)
#include <cuda_runtime.h>
#include <math.h>

#define Dk 512
#define Ek 8
#define Hk 128
#define MAXN 32768
#define CAPSTRIDE 5120
#define NBMAX (MAXN/256)

typedef unsigned long long ull;

// d = a * b + d  (elementwise f32x2) — FFMA2 in SASS
#define FMA2(d, a, b) asm("fma.rn.f32x2 %0, %1, %2, %0;" : "+l"(d) : "l"(a), "l"(b))
#define UNPACK2(lo, hi, d) do { unsigned _l, _h; \
    asm("mov.b64 {%0, %1}, %2;" : "=r"(_l), "=r"(_h) : "l"(d)); \
    lo = __uint_as_float(_l); hi = __uint_as_float(_h); } while(0)

// store {v, v} as one STS.64 (safe two-register form)
__device__ __forceinline__ void sts_dup(unsigned addr, float v) {
    unsigned u = __float_as_uint(v);
    asm volatile("{ .reg .b32 t; mov.b32 t, %1; st.shared.v2.b32 [%0], {%1, t}; }"
                 :: "r"(addr), "r"(u));
}

// ---------------- device scratch ----------------
__device__ int   g_top[MAXN];
__device__ float g_conf[MAXN];
__device__ int   g_boff[NBMAX*Ek];
__device__ int   g_list[Ek*CAPSTRIDE];
__device__ int   g_Me[Ek];
__device__ int   g_tile;

// ---------------- router ----------------
__global__ void router_kernel(const float* __restrict__ x,
                              const float* __restrict__ Wr,
                              const float* __restrict__ br, int N)
{
    __shared__ float sWr[Dk*Ek];
    int t = threadIdx.x;
    for (int i = t; i < Dk*Ek/4; i += 256)
        ((float4*)sWr)[i] = ((const float4*)Wr)[i];
    __syncthreads();

    int tok  = blockIdx.x*8 + (t >> 5);
    int lane = t & 31;
    if (tok >= N) return;
    const float* xr = x + (size_t)tok*Dk;

    float acc[Ek];
#pragma unroll
    for (int e = 0; e < Ek; e++) acc[e] = 0.f;

    for (int c = lane; c < Dk/4; c += 32) {
        float4 v = *(const float4*)(xr + c*4);
        const float* w = sWr + c*4*Ek;
        float xv[4] = {v.x, v.y, v.z, v.w};
#pragma unroll
        for (int kk = 0; kk < 4; kk++)
#pragma unroll
            for (int e = 0; e < Ek; e++)
                acc[e] = fmaf(xv[kk], w[kk*Ek + e], acc[e]);
    }
#pragma unroll
    for (int off = 16; off; off >>= 1)
#pragma unroll
        for (int e = 0; e < Ek; e++)
            acc[e] += __shfl_xor_sync(0xffffffffu, acc[e], off);

    if (lane == 0) {
        float v1 = -3e38f, v2 = -3e38f; int i1 = 0, i2 = 1;
#pragma unroll
        for (int e = 0; e < Ek; e++) {
            float v = acc[e] + br[e];
            if (v > v1)      { v2 = v1; i2 = i1; v1 = v; i1 = e; }
            else if (v > v2) { v2 = v;  i2 = e; }
        }
        g_top[tok]  = i1 | (i2 << 4);
        g_conf[tok] = v1;
    }
}

// ---------------- scanA: counts + prefix + stats (single block) ----------
__global__ void scanA_kernel(int NB, int N, int cap, float* tail)
{
    __shared__ int   cnt[NBMAX*Ek];
    __shared__ float csum[32];
    __shared__ int   tot[Ek];
    int t = threadIdx.x, lane = t & 31, w = t >> 5;

    float cpart = 0.f;
    for (int c = w; c < NB; c += 32) {
        int cnts[Ek];
#pragma unroll
        for (int e = 0; e < Ek; e++) cnts[e] = 0;
#pragma unroll
        for (int g = 0; g < 8; g++) {
            int idx = c*256 + g*32 + lane;
            int pk = -1; float cf = 0.f;
            if (idx < N) { pk = g_top[idx]; cf = g_conf[idx]; }
            cpart += cf;
#pragma unroll
            for (int e = 0; e < Ek; e++) {
                bool m = (pk >= 0) && (((pk & 15) == e) || (((pk >> 4) & 15) == e));
                cnts[e] += __popc(__ballot_sync(0xffffffffu, m));
            }
        }
        if (lane < Ek) cnt[c*Ek + lane] = cnts[lane];
    }
#pragma unroll
    for (int off = 16; off; off >>= 1)
        cpart += __shfl_xor_sync(0xffffffffu, cpart, off);
    if (lane == 0) csum[w] = cpart;
    __syncthreads();

    if (t < Ek) {
        int run = 0;
        for (int c = 0; c < NB; c++) { g_boff[c*Ek + t] = run; run += cnt[c*Ek + t]; }
        tot[t] = run;
        g_Me[t] = run < cap ? run : cap;
    }
    if (t == 0) g_tile = 0;
    __syncthreads();
    if (t == 0) {
        float s = 0.f, load[Ek];
        for (int i = 0; i < Ek; i++) {
            int l = tot[i] < cap ? tot[i] : cap;
            load[i] = (float)l; s += load[i];
        }
        float inv = 1.f / (s + 1e-8f);
        float loss = 0.f;
        for (int i = 0; i < Ek; i++) {
            float d = load[i] * inv;
            loss += d * logf(d + 1e-8f);
            tail[1 + i] = d;
        }
        tail[0] = loss;
        float cs = 0.f;
        for (int i = 0; i < 32; i++) cs += csum[i];
        tail[9] = cs / (float)N;
    }
}

// ---------------- scan3: compacted kept-token lists ----------------
__global__ void scan3_kernel(int N, int cap)
{
    __shared__ int spk[256];
    int t = threadIdx.x, b = blockIdx.x;
    int base = b*256;
    int lim = N - base; if (lim > 256) lim = 256;
    spk[t] = (t < lim) ? g_top[base + t] : -1;
    __syncthreads();
    int e = t >> 5, lane = t & 31;
    int run = g_boff[b*Ek + e];
#pragma unroll
    for (int r = 0; r < 8; r++) {
        int i = r*32 + lane;
        int pk = spk[i];
        bool m = (pk >= 0) && (((pk & 15) == e) || (((pk >> 4) & 15) == e));
        unsigned bal = __ballot_sync(0xffffffffu, m);
        if (m) {
            int idx = run + __popc(bal & ((1u << lane) - 1u));
            if (idx < cap) g_list[e*CAPSTRIDE + idx] = base + i;
        }
        run += __popc(bal);
    }
}

// ---------------- persistent fused FFN ----------------
// 128 threads (16 tx x 8 ty), tile MT=64 x 128, m-pair FFMA2 accumulators.
// a-side: natural m-pairs via LDS.128 from k-major Xs/Hs (broadcast).
// b-side: pre-duplicated interleaved weights Wd (conflict-free LDS.128).
#define MT 64
#define KT 16
#define HPAD 68
// smem layout (bytes)
#define XS_OFF   0                    // 2*16*64*4  =  8192
#define WD_OFF   8192                 // 2*16*128*8 = 32768
#define HS_OFF   40960                // 128*68*4   = 34816
#define ROWS_OFF 75776                // 64*4
#define SMEM_BYTES 76032

__global__ void __launch_bounds__(128, 3)
ffn_kernel(const float* __restrict__ x,  const float* __restrict__ W1,
           const float* __restrict__ b1, const float* __restrict__ W2,
           const float* __restrict__ b2, float* __restrict__ out,
           int ntiles, int tilesPerE)
{
    extern __shared__ char smem[];
    float* Xs   = (float*)(smem + XS_OFF);   // [2][KT][MT] k-major
    ull*   Wd   = (ull*)  (smem + WD_OFF);   // [2][KT][128] dup-interleaved
    float* Hs   = (float*)(smem + HS_OFF);   // [128][HPAD] k-major (H col major)
    int*   rows = (int*)  (smem + ROWS_OFF);
    __shared__ int s_tile;

    const unsigned wd_u32 = (unsigned)__cvta_generic_to_shared(Wd);

    int tid = threadIdx.x;
    int tx = tid & 15, ty = tid >> 4;
    int r  = tid >> 1, cA = (tid & 1)*8;       // X-gather map
    int kf = tid >> 3, nf = (tid & 7)*16;      // W-fill map

    // precompute dup-store addresses for the 16 W values this thread fills
    unsigned woff[16];
#pragma unroll
    for (int c = 0; c < 4; c++)
#pragma unroll
        for (int q = 0; q < 4; q++) {
            int n = nf + c*4 + q;
            woff[c*4+q] = (unsigned)((kf*128 + ((n & 7) >> 1)*32 + ((n >> 3) << 1) + (n & 1)) * 8);
        }
    const unsigned wbufstride = KT*128*8;

    for (;;) {
        __syncthreads();
        if (tid == 0) s_tile = atomicAdd(&g_tile, 1);
        __syncthreads();
        int t = s_tile;
        if (t >= ntiles) return;
        int e  = t / tilesPerE;
        int m0 = (t - e*tilesPerE) * MT;
        int Me = g_Me[e];
        if (m0 >= Me) continue;

        if (tid < MT) {
            int m = m0 + tid;
            rows[tid] = g_list[e*CAPSTRIDE + (m < Me ? m : (Me - 1))];
        }
        __syncthreads();

        const float* W1e = W1 + (size_t)e*Dk*Hk;
        const float* W2e = W2 + (size_t)e*Hk*Dk;
        const float* xrow = x + (size_t)rows[r]*Dk + cA;

        // ============ phase 1: Hs = relu(Xg @ W1 + b1), Hs k-major ============
        {   // prologue: stage 0 -> buf 0
            float4 av0 = *(const float4*)(xrow);
            float4 av1 = *(const float4*)(xrow + 4);
            float4 f0 = *(const float4*)(W1e + (size_t)kf*Hk + nf);
            float4 f1 = *(const float4*)(W1e + (size_t)kf*Hk + nf + 4);
            float4 f2 = *(const float4*)(W1e + (size_t)kf*Hk + nf + 8);
            float4 f3 = *(const float4*)(W1e + (size_t)kf*Hk + nf + 12);
            Xs[(cA+0)*MT+r]=av0.x; Xs[(cA+1)*MT+r]=av0.y; Xs[(cA+2)*MT+r]=av0.z; Xs[(cA+3)*MT+r]=av0.w;
            Xs[(cA+4)*MT+r]=av1.x; Xs[(cA+5)*MT+r]=av1.y; Xs[(cA+6)*MT+r]=av1.z; Xs[(cA+7)*MT+r]=av1.w;
            float wv[16] = {f0.x,f0.y,f0.z,f0.w, f1.x,f1.y,f1.z,f1.w,
                            f2.x,f2.y,f2.z,f2.w, f3.x,f3.y,f3.z,f3.w};
#pragma unroll
            for (int i = 0; i < 16; i++) sts_dup(wd_u32 + woff[i], wv[i]);
            __syncthreads();
        }

        ull acc[4][8];
#pragma unroll
        for (int p = 0; p < 4; p++)
#pragma unroll
            for (int j = 0; j < 8; j++) acc[p][j] = 0ull;

        for (int s = 0; s < Dk/KT; s++) {
            int cur = s & 1, nb = cur ^ 1;
            bool more = (s + 1 < Dk/KT);
            float4 av0, av1, f0, f1, f2, f3;
            if (more) {
                const float* ap = xrow + (s+1)*KT;
                av0 = *(const float4*)ap; av1 = *(const float4*)(ap + 4);
                const float* wp = W1e + (size_t)((s+1)*KT + kf)*Hk + nf;
                f0 = *(const float4*)wp;      f1 = *(const float4*)(wp + 4);
                f2 = *(const float4*)(wp + 8); f3 = *(const float4*)(wp + 12);
            }
#pragma unroll
            for (int k = 0; k < KT; k++) {
                const float* arow = Xs + (cur*KT + k)*MT;
                ulonglong2 a01 = *(const ulonglong2*)(arow + ty*8);
                ulonglong2 a23 = *(const ulonglong2*)(arow + ty*8 + 4);
                const ull* wrow = Wd + (size_t)(cur*KT + k)*128 + tx*2;
                ulonglong2 b0 = *(const ulonglong2*)(wrow);
                ulonglong2 b1r = *(const ulonglong2*)(wrow + 32);
                ulonglong2 b2r = *(const ulonglong2*)(wrow + 64);
                ulonglong2 b3r = *(const ulonglong2*)(wrow + 96);
                FMA2(acc[0][0],a01.x,b0.x); FMA2(acc[0][1],a01.x,b0.y);
                FMA2(acc[0][2],a01.x,b1r.x); FMA2(acc[0][3],a01.x,b1r.y);
                FMA2(acc[0][4],a01.x,b2r.x); FMA2(acc[0][5],a01.x,b2r.y);
                FMA2(acc[0][6],a01.x,b3r.x); FMA2(acc[0][7],a01.x,b3r.y);
                FMA2(acc[1][0],a01.y,b0.x); FMA2(acc[1][1],a01.y,b0.y);
                FMA2(acc[1][2],a01.y,b1r.x); FMA2(acc[1][3],a01.y,b1r.y);
                FMA2(acc[1][4],a01.y,b2r.x); FMA2(acc[1][5],a01.y,b2r.y);
                FMA2(acc[1][6],a01.y,b3r.x); FMA2(acc[1][7],a01.y,b3r.y);
                FMA2(acc[2][0],a23.x,b0.x); FMA2(acc[2][1],a23.x,b0.y);
                FMA2(acc[2][2],a23.x,b1r.x); FMA2(acc[2][3],a23.x,b1r.y);
                FMA2(acc[2][4],a23.x,b2r.x); FMA2(acc[2][5],a23.x,b2r.y);
                FMA2(acc[2][6],a23.x,b3r.x); FMA2(acc[2][7],a23.x,b3r.y);
                FMA2(acc[3][0],a23.y,b0.x); FMA2(acc[3][1],a23.y,b0.y);
                FMA2(acc[3][2],a23.y,b1r.x); FMA2(acc[3][3],a23.y,b1r.y);
                FMA2(acc[3][4],a23.y,b2r.x); FMA2(acc[3][5],a23.y,b2r.y);
                FMA2(acc[3][6],a23.y,b3r.x); FMA2(acc[3][7],a23.y,b3r.y);
            }
            if (more) {
                Xs[(nb*KT+cA+0)*MT+r]=av0.x; Xs[(nb*KT+cA+1)*MT+r]=av0.y;
                Xs[(nb*KT+cA+2)*MT+r]=av0.z; Xs[(nb*KT+cA+3)*MT+r]=av0.w;
                Xs[(nb*KT+cA+4)*MT+r]=av1.x; Xs[(nb*KT+cA+5)*MT+r]=av1.y;
                Xs[(nb*KT+cA+6)*MT+r]=av1.z; Xs[(nb*KT+cA+7)*MT+r]=av1.w;
                float wv[16] = {f0.x,f0.y,f0.z,f0.w, f1.x,f1.y,f1.z,f1.w,
                                f2.x,f2.y,f2.z,f2.w, f3.x,f3.y,f3.z,f3.w};
#pragma unroll
                for (int i = 0; i < 16; i++) sts_dup(wd_u32 + nb*wbufstride + woff[i], wv[i]);
            }
            __syncthreads();
        }

        // phase1 epilogue: relu+b1 -> Hs[hcol][m]  (+ phase2 prologue W2 chunk 0)
        {
            const float* b1e = b1 + e*Hk;
            float bb[8];
#pragma unroll
            for (int j = 0; j < 8; j++) bb[j] = b1e[tx*8 + j];
#pragma unroll
            for (int p = 0; p < 4; p++)
#pragma unroll
                for (int j = 0; j < 8; j++) {
                    float lo, hi;
                    UNPACK2(lo, hi, acc[p][j]);
                    Hs[(tx*8+j)*HPAD + ty*8 + 2*p]     = fmaxf(lo + bb[j], 0.f);
                    Hs[(tx*8+j)*HPAD + ty*8 + 2*p + 1] = fmaxf(hi + bb[j], 0.f);
                }
            const float* wp = W2e + (size_t)kf*Dk + nf;
            float4 f0 = *(const float4*)wp;      float4 f1 = *(const float4*)(wp + 4);
            float4 f2 = *(const float4*)(wp + 8); float4 f3 = *(const float4*)(wp + 12);
            float wv[16] = {f0.x,f0.y,f0.z,f0.w, f1.x,f1.y,f1.z,f1.w,
                            f2.x,f2.y,f2.z,f2.w, f3.x,f3.y,f3.z,f3.w};
#pragma unroll
            for (int i = 0; i < 16; i++) sts_dup(wd_u32 + woff[i], wv[i]);
            __syncthreads();
        }

        // ============ phase 2: out += Hs^T @ W2 + b2 ============
        ull acc2[4][8];
        for (int ss = 0; ss < 32; ss++) {
            int cur = ss & 1, nb = cur ^ 1;
            int n0 = ss >> 3, k0 = ss & 7;
            if (k0 == 0) {
#pragma unroll
                for (int p = 0; p < 4; p++)
#pragma unroll
                    for (int j = 0; j < 8; j++) acc2[p][j] = 0ull;
            }
            float4 f0, f1, f2, f3;
            bool more = (ss + 1 < 32);
            if (more) {
                int nn0 = (ss+1) >> 3, nk0 = (ss+1) & 7;
                const float* wp = W2e + (size_t)(nk0*KT + kf)*Dk + nn0*128 + nf;
                f0 = *(const float4*)wp;      f1 = *(const float4*)(wp + 4);
                f2 = *(const float4*)(wp + 8); f3 = *(const float4*)(wp + 12);
            }
#pragma unroll
            for (int k = 0; k < KT; k++) {
                const float* arow = Hs + (k0*KT + k)*HPAD;
                ulonglong2 a01 = *(const ulonglong2*)(arow + ty*8);
                ulonglong2 a23 = *(const ulonglong2*)(arow + ty*8 + 4);
                const ull* wrow = Wd + (size_t)(cur*KT + k)*128 + tx*2;
                ulonglong2 b0 = *(const ulonglong2*)(wrow);
                ulonglong2 b1r = *(const ulonglong2*)(wrow + 32);
                ulonglong2 b2r = *(const ulonglong2*)(wrow + 64);
                ulonglong2 b3r = *(const ulonglong2*)(wrow + 96);
                FMA2(acc2[0][0],a01.x,b0.x); FMA2(acc2[0][1],a01.x,b0.y);
                FMA2(acc2[0][2],a01.x,b1r.x); FMA2(acc2[0][3],a01.x,b1r.y);
                FMA2(acc2[0][4],a01.x,b2r.x); FMA2(acc2[0][5],a01.x,b2r.y);
                FMA2(acc2[0][6],a01.x,b3r.x); FMA2(acc2[0][7],a01.x,b3r.y);
                FMA2(acc2[1][0],a01.y,b0.x); FMA2(acc2[1][1],a01.y,b0.y);
                FMA2(acc2[1][2],a01.y,b1r.x); FMA2(acc2[1][3],a01.y,b1r.y);
                FMA2(acc2[1][4],a01.y,b2r.x); FMA2(acc2[1][5],a01.y,b2r.y);
                FMA2(acc2[1][6],a01.y,b3r.x); FMA2(acc2[1][7],a01.y,b3r.y);
                FMA2(acc2[2][0],a23.x,b0.x); FMA2(acc2[2][1],a23.x,b0.y);
                FMA2(acc2[2][2],a23.x,b1r.x); FMA2(acc2[2][3],a23.x,b1r.y);
                FMA2(acc2[2][4],a23.x,b2r.x); FMA2(acc2[2][5],a23.x,b2r.y);
                FMA2(acc2[2][6],a23.x,b3r.x); FMA2(acc2[2][7],a23.x,b3r.y);
                FMA2(acc2[3][0],a23.y,b0.x); FMA2(acc2[3][1],a23.y,b0.y);
                FMA2(acc2[3][2],a23.y,b1r.x); FMA2(acc2[3][3],a23.y,b1r.y);
                FMA2(acc2[3][4],a23.y,b2r.x); FMA2(acc2[3][5],a23.y,b2r.y);
                FMA2(acc2[3][6],a23.y,b3r.x); FMA2(acc2[3][7],a23.y,b3r.y);
            }
            if (more) {
                float wv[16] = {f0.x,f0.y,f0.z,f0.w, f1.x,f1.y,f1.z,f1.w,
                                f2.x,f2.y,f2.z,f2.w, f3.x,f3.y,f3.z,f3.w};
#pragma unroll
                for (int i = 0; i < 16; i++) sts_dup(wd_u32 + nb*wbufstride + woff[i], wv[i]);
            }
            __syncthreads();

            if (k0 == 7) {
                const float* b2e = b2 + (size_t)e*Dk + n0*128;
                float b2r8[8];
#pragma unroll
                for (int j = 0; j < 8; j++) b2r8[j] = b2e[tx*8 + j];
#pragma unroll
                for (int p = 0; p < 4; p++) {
                    int mA = ty*8 + 2*p, mB = mA + 1;
                    bool okA = (m0 + mA < Me), okB = (m0 + mB < Me);
                    float* opA = out + (size_t)rows[mA]*Dk + n0*128 + tx*8;
                    float* opB = out + (size_t)rows[mB]*Dk + n0*128 + tx*8;
#pragma unroll
                    for (int j = 0; j < 8; j++) {
                        float lo, hi;
                        UNPACK2(lo, hi, acc2[p][j]);
                        if (okA) atomicAdd(opA + j, lo + b2r8[j]);
                        if (okB) atomicAdd(opB + j, hi + b2r8[j]);
                    }
                }
            }
        }
    }
}

// ---------------- launch ----------------
extern "C" void kernel_launch(void* const* d_in, const int* in_sizes, int n_in,
                              void* d_out, int out_size)
{
    const float* x  = (const float*)d_in[0];
    const float* Wr = (const float*)d_in[1];
    const float* br = (const float*)d_in[2];
    const float* W1 = (const float*)d_in[3];
    const float* b1 = (const float*)d_in[4];
    const float* W2 = (const float*)d_in[5];
    const float* b2 = (const float*)d_in[6];
    float* out = (float*)d_out;

    int N = in_sizes[0] / Dk;
    if (N > MAXN) N = MAXN;
    int cap = (int)(1.25f * ((float)N / (float)Ek));
    if (cap > CAPSTRIDE) cap = CAPSTRIDE;
    int NB = (N + 255) / 256;

    static int smem_set = 0;
    if (!smem_set) {
        cudaFuncSetAttribute(ffn_kernel, cudaFuncAttributeMaxDynamicSharedMemorySize, SMEM_BYTES);
        smem_set = 1;
    }

    cudaMemsetAsync(d_out, 0, (size_t)out_size * sizeof(float), 0);
    router_kernel<<<(N + 7) / 8, 256>>>(x, Wr, br, N);
    scanA_kernel<<<1, 1024>>>(NB, N, cap, out + (size_t)N * Dk);
    scan3_kernel<<<NB, 256>>>(N, cap);

    int tilesPerE = (cap + MT - 1) / MT;
    int ntiles = tilesPerE * Ek;
    ffn_kernel<<<148*3, 128, SMEM_BYTES>>>(x, W1, b1, W2, b2, out, ntiles, tilesPerE);
}